// round 4
// baseline (speedup 1.0000x reference)
#include <cuda_runtime.h>
#include <cuda_fp16.h>

#define NUM_GROUPS   100
#define GROUP_SIZE   100
#define TOTAL_ROWS   10000
#define NUM_CLASSES  1000
#define NC_PAD       1024
#define BATCH        4096

// ---- static device scratch (no runtime allocation) ----
__device__ __half        g_Whalf[TOTAL_ROWS * NC_PAD];          // 20.97 MB padded fp16 W
__device__ float         g_part[4 * NUM_GROUPS * NC_PAD];       // partial (s1 + s2/2) sums
__device__ float         g_cconst[NC_PAD];                      // bias - sum_g lse (pad = -1e9)
__device__ unsigned char g_lidx[NUM_GROUPS * BATCH];            // local idx, layout [g][b]
__device__ float         g_logits[(size_t)BATCH * NC_PAD];      // padded logits

// ---------------------------------------------------------------------------
// K1: convert W -> padded fp16, and per (g,c) accumulate partial s1 + s2/2
//     over a 25-row chunk. grid (cblk=4, rsplit=4, g=100), 256 thr.
// ---------------------------------------------------------------------------
__global__ void __launch_bounds__(256) k1_prep(const float* __restrict__ W) {
    const int c  = blockIdx.x * 256 + threadIdx.x;   // 0..1023
    const int ry = blockIdx.y;                       // 0..3
    const int g  = blockIdx.z;                       // 0..99
    const int row0 = g * GROUP_SIZE + ry * 25;

    if (c >= NUM_CLASSES) {                          // zero the pad columns
        #pragma unroll 5
        for (int i = 0; i < 25; i++)
            g_Whalf[(size_t)(row0 + i) * NC_PAD + c] = __float2half(0.0f);
        return;
    }
    const float* base = W + (size_t)row0 * NUM_CLASSES + c;
    __half* hb = g_Whalf + (size_t)row0 * NC_PAD + c;
    float s1 = 0.0f, s2 = 0.0f;
    #pragma unroll 25
    for (int i = 0; i < 25; i++) {
        float w = base[(size_t)i * NUM_CLASSES];
        s1 += w;
        s2  = fmaf(w, w, s2);
        hb[(size_t)i * NC_PAD] = __float2half(w);
    }
    g_part[(ry * NUM_GROUPS + g) * NC_PAD + c] = s1 + 0.5f * s2;
}

// ---------------------------------------------------------------------------
// K2: cconst[c] = bias[c] - sum_g lse[g,c];  pad classes get -1e9
// ---------------------------------------------------------------------------
__global__ void __launch_bounds__(256) k2_const(const float* __restrict__ bias) {
    const int c = blockIdx.x * 256 + threadIdx.x;
    if (c >= NC_PAD) return;
    if (c >= NUM_CLASSES) { g_cconst[c] = -1e9f; return; }
    float S = 0.0f;
    #pragma unroll 10
    for (int g = 0; g < NUM_GROUPS; g++) {
        float p = g_part[(0 * NUM_GROUPS + g) * NC_PAD + c]
                + g_part[(1 * NUM_GROUPS + g) * NC_PAD + c]
                + g_part[(2 * NUM_GROUPS + g) * NC_PAD + c]
                + g_part[(3 * NUM_GROUPS + g) * NC_PAD + c];
        // lse = log(100) + log1p((s1 + s2/2)/100)   (Taylor err ~1e-7)
        S += 4.6051701860f + log1pf(p * 0.01f);
    }
    g_cconst[c] = bias[c] - S;
}

// ---------------------------------------------------------------------------
// K3: scan one-hot rows -> u8 local indices, layout [g][b] for coalesced
//     per-group loads in the gather kernel. One CTA per sample.
// ---------------------------------------------------------------------------
__global__ void __launch_bounds__(256) k3_scan(const float* __restrict__ X) {
    const int b = blockIdx.x;
    const int t = threadIdx.x;
    const float4* xr = reinterpret_cast<const float4*>(X + (size_t)b * TOTAL_ROWS);
    for (int i = t; i < TOTAL_ROWS / 4; i += 256) {
        float4 v = xr[i];
        int col = 4 * i;
        #pragma unroll
        for (int k = 0; k < 4; k++) {
            float f = (k == 0) ? v.x : (k == 1) ? v.y : (k == 2) ? v.z : v.w;
            if (f > 0.5f) {
                int cc = col + k;
                int g  = (cc * 5243) >> 19;          // cc/100 for cc < 10486
                g_lidx[g * BATCH + b] = (unsigned char)(cc - g * 100);
            }
        }
    }
}

// ---------------------------------------------------------------------------
// K4: smem-staged gather. CTA = (class chunk of 64, sample block of 512).
//     grid (16, 8) = 128 CTAs, 512 threads (16 warps x 32 samples).
//     Per group g: W_g slice [100][64] fp16 staged in smem (double-buffered
//     cp.async), then every sample does one conflict-free broadcast-row
//     LDS.32 + HADD2 per 64 classes. Dual fp16 accumulators by g-parity.
// ---------------------------------------------------------------------------
__device__ __forceinline__ void cpa16(unsigned int dst, const void* src) {
    asm volatile("cp.async.ca.shared.global [%0], [%1], 16;\n"
                 :: "r"(dst), "l"(src) : "memory");
}

__global__ void __launch_bounds__(512, 1) k4_gather() {
    __shared__ __align__(16) unsigned int  sW[2][GROUP_SIZE * 32];   // [100 rows][32 half2]
    __shared__ __align__(16) unsigned char sIdx[2][512];

    const int tid = threadIdx.x;
    const int w   = tid >> 5;          // warp 0..15
    const int l   = tid & 31;          // lane
    const int n0  = blockIdx.x * 64;   // class chunk base
    const int b0  = blockIdx.y * 512;  // sample block base

    unsigned int sW_base, sI_base;
    {
        unsigned long long a;
        asm("cvta.to.shared.u64 %0, %1;" : "=l"(a) : "l"((void*)&sW[0][0]));
        sW_base = (unsigned int)a;
        asm("cvta.to.shared.u64 %0, %1;" : "=l"(a) : "l"((void*)&sIdx[0][0]));
        sI_base = (unsigned int)a;
    }

    // stage loader: W slice for group g -> buf, idx row -> buf
    auto stage = [&](int g, int buf) {
        // W: 100 rows x 128B = 800 x 16B
        {
            int i = tid;  // < 512
            const __half* src = g_Whalf + (size_t)(g * GROUP_SIZE + (i >> 3)) * NC_PAD
                                        + n0 + ((i & 7) << 3);
            cpa16(sW_base + buf * (GROUP_SIZE * 128) + i * 16, src);
            i += 512;
            if (i < 800) {
                const __half* src2 = g_Whalf + (size_t)(g * GROUP_SIZE + (i >> 3)) * NC_PAD
                                             + n0 + ((i & 7) << 3);
                cpa16(sW_base + buf * (GROUP_SIZE * 128) + i * 16, src2);
            }
        }
        // idx: 512B = 32 x 16B
        if (tid < 32) {
            const unsigned char* src = g_lidx + g * BATCH + b0 + tid * 16;
            cpa16(sI_base + buf * 512 + tid * 16, src);
        }
        asm volatile("cp.async.commit_group;\n" ::: "memory");
    };

    __half2 accA[32], accB[32];
    #pragma unroll
    for (int j = 0; j < 32; j++) { accA[j] = __half2half2(__ushort_as_half(0)); accB[j] = accA[j]; }

    stage(0, 0);

    for (int g = 0; g < NUM_GROUPS; g++) {
        const int buf = g & 1;
        if (g + 1 < NUM_GROUPS) {
            stage(g + 1, buf ^ 1);
            asm volatile("cp.async.wait_group 1;\n" ::: "memory");
        } else {
            asm volatile("cp.async.wait_group 0;\n" ::: "memory");
        }
        __syncthreads();

        const unsigned int* wrow = &sW[buf][0];
        // 32 sample indices for this warp, as 2 x uint4 broadcast reads
        const uint4* ip = reinterpret_cast<const uint4*>(&sIdx[buf][w * 32]);

        #pragma unroll
        for (int half = 0; half < 2; half++) {
            uint4 p = ip[half];
            #pragma unroll
            for (int q = 0; q < 4; q++) {
                unsigned int word = (q == 0) ? p.x : (q == 1) ? p.y : (q == 2) ? p.z : p.w;
                #pragma unroll
                for (int k = 0; k < 4; k++) {
                    int r = (word >> (8 * k)) & 0xFF;
                    unsigned int v = wrow[r * 32 + l];   // conflict-free: bank == lane
                    int j = half * 16 + q * 4 + k;
                    __half2 h = *reinterpret_cast<__half2*>(&v);
                    if (buf) accB[j] = __hadd2(accB[j], h);
                    else     accA[j] = __hadd2(accA[j], h);
                }
            }
        }
        __syncthreads();
    }

    // epilogue: merge accumulators in fp32, add class constant, store padded logits
    float2 cc = *reinterpret_cast<const float2*>(g_cconst + n0 + 2 * l);
    #pragma unroll
    for (int j = 0; j < 32; j++) {
        float2 a = __half22float2(accA[j]);
        float2 b = __half22float2(accB[j]);
        float2 o;
        o.x = a.x + b.x + cc.x;
        o.y = a.y + b.y + cc.y;
        size_t off = (size_t)(b0 + w * 32 + j) * NC_PAD + n0 + 2 * l;
        *reinterpret_cast<float2*>(g_logits + off) = o;
    }
}

// ---------------------------------------------------------------------------
// K5: softmax over padded logits (pad classes are -1e9 -> exp = 0).
// ---------------------------------------------------------------------------
__global__ void __launch_bounds__(256) k5_softmax(float* __restrict__ out) {
    __shared__ float s_red[8];
    const int b = blockIdx.x;
    const int t = threadIdx.x;

    float4 v = reinterpret_cast<const float4*>(g_logits + (size_t)b * NC_PAD)[t];

    float m = fmaxf(fmaxf(v.x, v.y), fmaxf(v.z, v.w));
    #pragma unroll
    for (int o = 16; o > 0; o >>= 1)
        m = fmaxf(m, __shfl_xor_sync(0xffffffffu, m, o));
    if ((t & 31) == 0) s_red[t >> 5] = m;
    __syncthreads();
    float M = s_red[0];
    #pragma unroll
    for (int i = 1; i < 8; i++) M = fmaxf(M, s_red[i]);
    __syncthreads();

    float e0 = __expf(v.x - M), e1 = __expf(v.y - M);
    float e2 = __expf(v.z - M), e3 = __expf(v.w - M);
    float s = (e0 + e1) + (e2 + e3);
    #pragma unroll
    for (int o = 16; o > 0; o >>= 1)
        s += __shfl_xor_sync(0xffffffffu, s, o);
    if ((t & 31) == 0) s_red[t >> 5] = s;
    __syncthreads();
    float T = 0.f;
    #pragma unroll
    for (int i = 0; i < 8; i++) T += s_red[i];
    float inv = 1.0f / T;

    if (t < 250) {
        float4 o4; o4.x = e0 * inv; o4.y = e1 * inv; o4.z = e2 * inv; o4.w = e3 * inv;
        reinterpret_cast<float4*>(out + (size_t)b * NUM_CLASSES)[t] = o4;
    }
}

// ---------------------------------------------------------------------------
extern "C" void kernel_launch(void* const* d_in, const int* in_sizes, int n_in,
                              void* d_out, int out_size) {
    const float* x    = (const float*)d_in[0];  // (4096, 10000) f32
    const float* W    = (const float*)d_in[1];  // (10000, 1000) f32
    const float* bias = (const float*)d_in[2];  // (1000,) f32
    float* out = (float*)d_out;                 // (4096, 1000) f32

    k3_scan<<<BATCH, 256>>>(x);
    k1_prep<<<dim3(4, 4, NUM_GROUPS), 256>>>(W);
    k2_const<<<4, 256>>>(bias);
    k4_gather<<<dim3(16, 8), 512>>>();
    k5_softmax<<<BATCH, 256>>>(out);
}

// round 5
// speedup vs baseline: 1.0628x; 1.0628x over previous
#include <cuda_runtime.h>
#include <cuda_fp16.h>

#define NUM_GROUPS   100
#define GROUP_SIZE   100
#define TOTAL_ROWS   10000
#define NUM_CLASSES  1000
#define NC_PAD       1024
#define BATCH        4096

// ---- static device scratch (no runtime allocation) ----
__device__ __half        g_Whalf[TOTAL_ROWS * NC_PAD];          // 20.97 MB padded fp16 W
__device__ float         g_part[4 * NUM_GROUPS * NC_PAD];       // partial (s1 + s2/2) sums
__device__ float         g_cconst[NC_PAD];                      // bias - sum_g lse (pad = -1e9)
__device__ unsigned char g_lidx[NUM_GROUPS * BATCH];            // local idx, layout [g][b]
__device__ __half        g_logitsh[(size_t)BATCH * NC_PAD];     // centered logits, fp16

// ---------------------------------------------------------------------------
// K1: W -> padded fp16 + partial (s1 + s2/2) over 25-row chunks.
//     grid (cblk=4, rsplit=4, g=100), 256 thr.
// ---------------------------------------------------------------------------
__global__ void __launch_bounds__(256) k1_prep(const float* __restrict__ W) {
    const int c  = blockIdx.x * 256 + threadIdx.x;   // 0..1023
    const int ry = blockIdx.y;                       // 0..3
    const int g  = blockIdx.z;                       // 0..99
    const int row0 = g * GROUP_SIZE + ry * 25;

    if (c >= NUM_CLASSES) {                          // zero the pad columns
        #pragma unroll 5
        for (int i = 0; i < 25; i++)
            g_Whalf[(size_t)(row0 + i) * NC_PAD + c] = __float2half(0.0f);
        return;
    }
    const float* base = W + (size_t)row0 * NUM_CLASSES + c;
    __half* hb = g_Whalf + (size_t)row0 * NC_PAD + c;
    float s1 = 0.0f, s2 = 0.0f;
    #pragma unroll 25
    for (int i = 0; i < 25; i++) {
        float w = base[(size_t)i * NUM_CLASSES];
        s1 += w;
        s2  = fmaf(w, w, s2);
        hb[(size_t)i * NC_PAD] = __float2half(w);
    }
    g_part[(ry * NUM_GROUPS + g) * NC_PAD + c] = s1 + 0.5f * s2;
}

// ---------------------------------------------------------------------------
// K2: cconst[c] = bias[c] - sum_g lse[g,c];  pad classes get -1e9
// ---------------------------------------------------------------------------
__global__ void __launch_bounds__(256) k2_const(const float* __restrict__ bias) {
    const int c = blockIdx.x * 256 + threadIdx.x;
    if (c >= NC_PAD) return;
    if (c >= NUM_CLASSES) { g_cconst[c] = -1e9f; return; }
    float S = 0.0f;
    #pragma unroll 10
    for (int g = 0; g < NUM_GROUPS; g++) {
        float p = g_part[(0 * NUM_GROUPS + g) * NC_PAD + c]
                + g_part[(1 * NUM_GROUPS + g) * NC_PAD + c]
                + g_part[(2 * NUM_GROUPS + g) * NC_PAD + c]
                + g_part[(3 * NUM_GROUPS + g) * NC_PAD + c];
        S += 4.6051701860f + log1pf(p * 0.01f);      // lse Taylor, err ~1e-7
    }
    g_cconst[c] = bias[c] - S;
}

// ---------------------------------------------------------------------------
// K3: scan one-hot rows -> u8 local indices [g][b]. One CTA per sample.
//     Loads batched into registers (MLP=9) before testing.
// ---------------------------------------------------------------------------
__global__ void __launch_bounds__(256) k3_scan(const float* __restrict__ X) {
    const int b = blockIdx.x;
    const int t = threadIdx.x;
    const float4* xr = reinterpret_cast<const float4*>(X + (size_t)b * TOTAL_ROWS);

    float4 vv[9];
    #pragma unroll
    for (int ii = 0; ii < 9; ii++) vv[ii] = xr[t + ii * 256];   // 2304 <= 2500 ok

    #pragma unroll
    for (int ii = 0; ii < 9; ii++) {
        int col = 4 * (t + ii * 256);
        #pragma unroll
        for (int k = 0; k < 4; k++) {
            float f = (k == 0) ? vv[ii].x : (k == 1) ? vv[ii].y
                    : (k == 2) ? vv[ii].z : vv[ii].w;
            if (f != 0.0f) {
                int cc = col + k;
                int g  = (cc * 5243) >> 19;          // cc/100 for cc < 10486
                g_lidx[g * BATCH + b] = (unsigned char)(cc - g * 100);
            }
        }
    }
    {   // tail: i in [2304, 2500)
        int i = t + 2304;
        if (i < 2500) {
            float4 v = xr[i];
            int col = 4 * i;
            #pragma unroll
            for (int k = 0; k < 4; k++) {
                float f = (k == 0) ? v.x : (k == 1) ? v.y : (k == 2) ? v.z : v.w;
                if (f != 0.0f) {
                    int cc = col + k;
                    int g  = (cc * 5243) >> 19;
                    g_lidx[g * BATCH + b] = (unsigned char)(cc - g * 100);
                }
            }
        }
    }
}

// ---------------------------------------------------------------------------
// K4: smem-staged gather, LDS.64 half-warp row pairing.
//     CTA = (64-class chunk, 512-sample block); grid (16, 8) = 128 CTAs,
//     512 threads = 16 warps x 32 samples.
//     Lane half h = l>>4 picks sample parity; lane c16 = l&15 picks 4 classes.
//     Per (sample pair, group): one LDS.64 per lane (conflict-free per phase)
//     + 2 HADD2. Indices via broadcast LDS.U8. Dual fp16 acc by g-parity.
// ---------------------------------------------------------------------------
__device__ __forceinline__ void cpa16(unsigned int dst, const void* src) {
    asm volatile("cp.async.ca.shared.global [%0], [%1], 16;\n"
                 :: "r"(dst), "l"(src) : "memory");
}

__global__ void __launch_bounds__(512, 1) k4_gather() {
    __shared__ __align__(16) uint2        sW[2][GROUP_SIZE * 16];  // [100 rows][16 uint2=128B]
    __shared__ __align__(16) unsigned char sIdx[2][512];

    const int tid = threadIdx.x;
    const int w   = tid >> 5;          // warp 0..15
    const int l   = tid & 31;          // lane
    const int h   = l >> 4;            // half-warp: sample parity
    const int c16 = l & 15;            // 4-class slot within the 64-class chunk
    const int n0  = blockIdx.x * 64;   // class chunk base
    const int b0  = blockIdx.y * 512;  // sample block base

    unsigned int sW_base, sI_base;
    {
        unsigned long long a;
        asm("cvta.to.shared.u64 %0, %1;" : "=l"(a) : "l"((void*)&sW[0][0]));
        sW_base = (unsigned int)a;
        asm("cvta.to.shared.u64 %0, %1;" : "=l"(a) : "l"((void*)&sIdx[0][0]));
        sI_base = (unsigned int)a;
    }

    auto stage = [&](int g, int buf) {
        // W slice: 100 rows x 128B = 800 x 16B chunks
        {
            int i = tid;  // < 512
            const __half* src = g_Whalf + (size_t)(g * GROUP_SIZE + (i >> 3)) * NC_PAD
                                        + n0 + ((i & 7) << 3);
            cpa16(sW_base + buf * (GROUP_SIZE * 128) + i * 16, src);
            i += 512;
            if (i < 800) {
                const __half* src2 = g_Whalf + (size_t)(g * GROUP_SIZE + (i >> 3)) * NC_PAD
                                             + n0 + ((i & 7) << 3);
                cpa16(sW_base + buf * (GROUP_SIZE * 128) + i * 16, src2);
            }
        }
        // idx: 512B = 32 x 16B
        if (tid < 32) {
            const unsigned char* src = g_lidx + g * BATCH + b0 + tid * 16;
            cpa16(sI_base + buf * 512 + tid * 16, src);
        }
        asm volatile("cp.async.commit_group;\n" ::: "memory");
    };

    __half2 aA0[16], aA1[16], aB0[16], aB1[16];
    #pragma unroll
    for (int q = 0; q < 16; q++) {
        aA0[q] = __half2half2(__ushort_as_half(0));
        aA1[q] = aA0[q]; aB0[q] = aA0[q]; aB1[q] = aA0[q];
    }

    stage(0, 0);

    for (int g = 0; g < NUM_GROUPS; g++) {
        const int buf = g & 1;
        if (g + 1 < NUM_GROUPS) {
            stage(g + 1, buf ^ 1);
            asm volatile("cp.async.wait_group 1;\n" ::: "memory");
        } else {
            asm volatile("cp.async.wait_group 0;\n" ::: "memory");
        }
        __syncthreads();

        const uint2* wbuf = &sW[buf][0];
        const unsigned char* ibuf = &sIdx[buf][w * 32];

        if (g & 1) {
            #pragma unroll
            for (int q = 0; q < 16; q++) {
                int r = ibuf[2 * q + h];                 // broadcast LDS.U8
                uint2 v = wbuf[r * 16 + c16];            // LDS.64, conflict-free phases
                aB0[q] = __hadd2(aB0[q], *reinterpret_cast<__half2*>(&v.x));
                aB1[q] = __hadd2(aB1[q], *reinterpret_cast<__half2*>(&v.y));
            }
        } else {
            #pragma unroll
            for (int q = 0; q < 16; q++) {
                int r = ibuf[2 * q + h];
                uint2 v = wbuf[r * 16 + c16];
                aA0[q] = __hadd2(aA0[q], *reinterpret_cast<__half2*>(&v.x));
                aA1[q] = __hadd2(aA1[q], *reinterpret_cast<__half2*>(&v.y));
            }
        }
        __syncthreads();
    }

    // epilogue: merge parity accumulators, store centered fp16 logits
    #pragma unroll
    for (int q = 0; q < 16; q++) {
        int sample = b0 + w * 32 + 2 * q + h;
        uint2 o;
        __half2 m0 = __hadd2(aA0[q], aB0[q]);
        __half2 m1 = __hadd2(aA1[q], aB1[q]);
        o.x = *reinterpret_cast<unsigned int*>(&m0);
        o.y = *reinterpret_cast<unsigned int*>(&m1);
        *reinterpret_cast<uint2*>(g_logitsh + (size_t)sample * NC_PAD + n0 + 4 * c16) = o;
    }
}

// ---------------------------------------------------------------------------
// K5: softmax. Loads centered fp16 logits + f32 cconst (pad = -1e9 -> exp 0).
// ---------------------------------------------------------------------------
__global__ void __launch_bounds__(256) k5_softmax(float* __restrict__ out) {
    __shared__ float s_red[8];
    const int b = blockIdx.x;
    const int t = threadIdx.x;

    uint2 raw = reinterpret_cast<const uint2*>(g_logitsh + (size_t)b * NC_PAD)[t];
    float4 cc = reinterpret_cast<const float4*>(g_cconst)[t];
    float2 f0 = __half22float2(*reinterpret_cast<__half2*>(&raw.x));
    float2 f1 = __half22float2(*reinterpret_cast<__half2*>(&raw.y));
    float4 v;
    v.x = f0.x + cc.x; v.y = f0.y + cc.y;
    v.z = f1.x + cc.z; v.w = f1.y + cc.w;

    float m = fmaxf(fmaxf(v.x, v.y), fmaxf(v.z, v.w));
    #pragma unroll
    for (int o = 16; o > 0; o >>= 1)
        m = fmaxf(m, __shfl_xor_sync(0xffffffffu, m, o));
    if ((t & 31) == 0) s_red[t >> 5] = m;
    __syncthreads();
    float M = s_red[0];
    #pragma unroll
    for (int i = 1; i < 8; i++) M = fmaxf(M, s_red[i]);
    __syncthreads();

    float e0 = __expf(v.x - M), e1 = __expf(v.y - M);
    float e2 = __expf(v.z - M), e3 = __expf(v.w - M);
    float s = (e0 + e1) + (e2 + e3);
    #pragma unroll
    for (int o = 16; o > 0; o >>= 1)
        s += __shfl_xor_sync(0xffffffffu, s, o);
    if ((t & 31) == 0) s_red[t >> 5] = s;
    __syncthreads();
    float T = 0.f;
    #pragma unroll
    for (int i = 0; i < 8; i++) T += s_red[i];
    float inv = 1.0f / T;

    if (t < 250) {
        float4 o4; o4.x = e0 * inv; o4.y = e1 * inv; o4.z = e2 * inv; o4.w = e3 * inv;
        reinterpret_cast<float4*>(out + (size_t)b * NUM_CLASSES)[t] = o4;
    }
}

// ---------------------------------------------------------------------------
extern "C" void kernel_launch(void* const* d_in, const int* in_sizes, int n_in,
                              void* d_out, int out_size) {
    const float* x    = (const float*)d_in[0];  // (4096, 10000) f32
    const float* W    = (const float*)d_in[1];  // (10000, 1000) f32
    const float* bias = (const float*)d_in[2];  // (1000,) f32
    float* out = (float*)d_out;                 // (4096, 1000) f32

    k3_scan<<<BATCH, 256>>>(x);
    k1_prep<<<dim3(4, 4, NUM_GROUPS), 256>>>(W);
    k2_const<<<4, 256>>>(bias);
    k4_gather<<<dim3(16, 8), 512>>>();
    k5_softmax<<<BATCH, 256>>>(out);
}

// round 6
// speedup vs baseline: 1.2431x; 1.1696x over previous
#include <cuda_runtime.h>
#include <cuda_fp16.h>

#define NUM_GROUPS   100
#define GROUP_SIZE   100
#define TOTAL_ROWS   10000
#define NUM_CLASSES  1000
#define NC_PAD       1024
#define BATCH        4096

// ---- static device scratch (no runtime allocation) ----
__device__ __half        g_Whalf[TOTAL_ROWS * NC_PAD];          // 20.97 MB padded fp16 W
__device__ float         g_part[NUM_GROUPS * NC_PAD];           // (s1 + s2/2) per (g,c)
__device__ float         g_cconst[NC_PAD];                      // bias - sum_g lse (pad = -1e9)
__device__ unsigned char g_lidx[NUM_GROUPS * BATCH];            // local idx, layout [g][b]
__device__ __half        g_logitsh[(size_t)BATCH * NC_PAD];     // centered logits, fp16

// ---------------------------------------------------------------------------
// K1: W -> padded fp16 + (s1 + s2/2) per (g,c). grid (4, 100), 256 thr.
//     Loads batched 10 at a time for MLP.
// ---------------------------------------------------------------------------
__global__ void __launch_bounds__(256) k1_prep(const float* __restrict__ W) {
    const int c = blockIdx.x * 256 + threadIdx.x;    // 0..1023
    const int g = blockIdx.y;                        // 0..99
    const int row0 = g * GROUP_SIZE;

    if (c >= NUM_CLASSES) {                          // zero pad columns
        __half* hb = g_Whalf + (size_t)row0 * NC_PAD + c;
        #pragma unroll 10
        for (int i = 0; i < GROUP_SIZE; i++)
            hb[(size_t)i * NC_PAD] = __float2half(0.0f);
        return;
    }
    const float* base = W + (size_t)row0 * NUM_CLASSES + c;
    __half* hb = g_Whalf + (size_t)row0 * NC_PAD + c;
    float s1 = 0.0f, s2 = 0.0f;
    #pragma unroll
    for (int rb = 0; rb < 10; rb++) {
        float wv[10];
        #pragma unroll
        for (int i = 0; i < 10; i++)
            wv[i] = base[(size_t)(rb * 10 + i) * NUM_CLASSES];
        #pragma unroll
        for (int i = 0; i < 10; i++) {
            s1 += wv[i];
            s2  = fmaf(wv[i], wv[i], s2);
            hb[(size_t)(rb * 10 + i) * NC_PAD] = __float2half(wv[i]);
        }
    }
    g_part[g * NC_PAD + c] = s1 + 0.5f * s2;
}

// ---------------------------------------------------------------------------
// K2: cconst[c] = bias[c] - sum_g lse[g,c];  pad classes get -1e9
// ---------------------------------------------------------------------------
__global__ void __launch_bounds__(256) k2_const(const float* __restrict__ bias) {
    const int c = blockIdx.x * 256 + threadIdx.x;
    if (c >= NC_PAD) return;
    if (c >= NUM_CLASSES) { g_cconst[c] = -1e9f; return; }
    float S = 0.0f;
    #pragma unroll 10
    for (int g = 0; g < NUM_GROUPS; g++)
        S += 4.6051701860f + log1pf(g_part[g * NC_PAD + c] * 0.01f);  // lse Taylor
    g_cconst[c] = bias[c] - S;
}

// ---------------------------------------------------------------------------
// K3: scan one-hot rows -> u8 local indices [g][b]. One CTA per sample.
//     250 threads x 10 uint4 loads (MLP=10), bit-pattern nonzero test.
// ---------------------------------------------------------------------------
__global__ void __launch_bounds__(256) k3_scan(const float* __restrict__ X) {
    const int b = blockIdx.x;
    const int t = threadIdx.x;
    if (t >= 250) return;
    const uint4* xr = reinterpret_cast<const uint4*>(X + (size_t)b * TOTAL_ROWS);

    uint4 vv[10];
    #pragma unroll
    for (int i = 0; i < 10; i++) vv[i] = xr[t + i * 250];   // 2500 exactly

    #pragma unroll
    for (int i = 0; i < 10; i++) {
        int col = 4 * (t + i * 250);
        unsigned int u[4] = {vv[i].x, vv[i].y, vv[i].z, vv[i].w};
        #pragma unroll
        for (int k = 0; k < 4; k++) {
            if (u[k] != 0u) {
                int cc = col + k;
                int g  = (cc * 5243) >> 19;          // cc/100 for cc < 10486
                g_lidx[g * BATCH + b] = (unsigned char)(cc - g * 100);
            }
        }
    }
}

// ---------------------------------------------------------------------------
// K4: smem-staged gather. CTA = 64 classes x 512 samples, grid (16,8)=128,
//     1024 threads = 32 warps x 16 samples. Triple-buffered cp.async W
//     staging, ONE __syncthreads per group. Warp's 16 sample indices loaded
//     as one broadcast LDS.128, bytes extracted in registers.
//     Thread: h = l>>4 sample parity, c16 = l&15 -> 4 classes; 8 samples.
// ---------------------------------------------------------------------------
__device__ __forceinline__ void cpa16(unsigned int dst, const void* src) {
    asm volatile("cp.async.ca.shared.global [%0], [%1], 16;\n"
                 :: "r"(dst), "l"(src) : "memory");
}
__device__ __forceinline__ void cpa_commit() {
    asm volatile("cp.async.commit_group;\n" ::: "memory");
}
__device__ __forceinline__ void cpa_wait1() {
    asm volatile("cp.async.wait_group 1;\n" ::: "memory");
}
__device__ __forceinline__ void cpa_wait0() {
    asm volatile("cp.async.wait_group 0;\n" ::: "memory");
}

__global__ void __launch_bounds__(1024, 1) k4_gather() {
    __shared__ __align__(16) uint2         sW[3][GROUP_SIZE * 16];  // 3 x 12.8 KB
    __shared__ __align__(16) unsigned char sIdx[3][512];

    const int tid = threadIdx.x;
    const int w   = tid >> 5;          // warp 0..31
    const int l   = tid & 31;
    const int h   = l >> 4;            // sample parity
    const int c16 = l & 15;            // 4-class slot
    const int n0  = blockIdx.x * 64;   // class chunk base
    const int b0  = blockIdx.y * 512;  // sample block base

    unsigned int sW_base, sI_base;
    {
        unsigned long long a;
        asm("cvta.to.shared.u64 %0, %1;" : "=l"(a) : "l"((void*)&sW[0][0]));
        sW_base = (unsigned int)a;
        asm("cvta.to.shared.u64 %0, %1;" : "=l"(a) : "l"((void*)&sIdx[0][0]));
        sI_base = (unsigned int)a;
    }

    auto stage = [&](int g, int buf) {
        if (tid < 800) {               // 100 rows x 128B = 800 x 16B
            const __half* src = g_Whalf + (size_t)(g * GROUP_SIZE + (tid >> 3)) * NC_PAD
                                        + n0 + ((tid & 7) << 3);
            cpa16(sW_base + buf * (GROUP_SIZE * 128) + tid * 16, src);
        }
        if (tid < 32) {                // 512B idx
            const unsigned char* src = g_lidx + g * BATCH + b0 + tid * 16;
            cpa16(sI_base + buf * 512 + tid * 16, src);
        }
        cpa_commit();
    };

    __half2 a0[8], a1[8];
    #pragma unroll
    for (int q = 0; q < 8; q++) {
        a0[q] = __half2half2(__ushort_as_half(0));
        a1[q] = a0[q];
    }

    stage(0, 0);
    stage(1, 1);

    int buf = 0;
    for (int g = 0; g < NUM_GROUPS; g++) {
        if (g == NUM_GROUPS - 1) cpa_wait0(); else cpa_wait1();
        __syncthreads();
        if (g + 2 < NUM_GROUPS) {
            int nb = buf + 2; if (nb >= 3) nb -= 3;
            stage(g + 2, nb);
        }

        const uint2* wbuf = &sW[buf][0];
        // warp's 16 sample indices: one broadcast 16B load
        uint4 ip = *reinterpret_cast<const uint4*>(&sIdx[buf][w * 16]);
        const int shbase = h * 8;      // byte position within half-pair

        #pragma unroll
        for (int q = 0; q < 8; q++) {
            unsigned int word = (q < 2) ? ip.x : (q < 4) ? ip.y : (q < 6) ? ip.z : ip.w;
            int shift = ((q & 1) << 4) + shbase;        // ((2q+h)&3)*8
            int r = (word >> shift) & 0xFF;
            uint2 v = wbuf[r * 16 + c16];               // LDS.64, 2-phase, no extra conflicts
            a0[q] = __hadd2(a0[q], *reinterpret_cast<__half2*>(&v.x));
            a1[q] = __hadd2(a1[q], *reinterpret_cast<__half2*>(&v.y));
        }
        buf++; if (buf == 3) buf = 0;
    }

    // epilogue: store centered fp16 logits
    #pragma unroll
    for (int q = 0; q < 8; q++) {
        int sample = b0 + w * 16 + 2 * q + h;
        uint2 o;
        o.x = *reinterpret_cast<unsigned int*>(&a0[q]);
        o.y = *reinterpret_cast<unsigned int*>(&a1[q]);
        *reinterpret_cast<uint2*>(g_logitsh + (size_t)sample * NC_PAD + n0 + 4 * c16) = o;
    }
}

// ---------------------------------------------------------------------------
// K5: softmax. fp16 centered logits + f32 cconst (pad -> exp 0).
// ---------------------------------------------------------------------------
__global__ void __launch_bounds__(256) k5_softmax(float* __restrict__ out) {
    __shared__ float s_red[8];
    const int b = blockIdx.x;
    const int t = threadIdx.x;

    uint2 raw = reinterpret_cast<const uint2*>(g_logitsh + (size_t)b * NC_PAD)[t];
    float4 cc = reinterpret_cast<const float4*>(g_cconst)[t];
    float2 f0 = __half22float2(*reinterpret_cast<__half2*>(&raw.x));
    float2 f1 = __half22float2(*reinterpret_cast<__half2*>(&raw.y));
    float4 v;
    v.x = f0.x + cc.x; v.y = f0.y + cc.y;
    v.z = f1.x + cc.z; v.w = f1.y + cc.w;

    float m = fmaxf(fmaxf(v.x, v.y), fmaxf(v.z, v.w));
    #pragma unroll
    for (int o = 16; o > 0; o >>= 1)
        m = fmaxf(m, __shfl_xor_sync(0xffffffffu, m, o));
    if ((t & 31) == 0) s_red[t >> 5] = m;
    __syncthreads();
    float M = s_red[0];
    #pragma unroll
    for (int i = 1; i < 8; i++) M = fmaxf(M, s_red[i]);
    __syncthreads();

    float e0 = __expf(v.x - M), e1 = __expf(v.y - M);
    float e2 = __expf(v.z - M), e3 = __expf(v.w - M);
    float s = (e0 + e1) + (e2 + e3);
    #pragma unroll
    for (int o = 16; o > 0; o >>= 1)
        s += __shfl_xor_sync(0xffffffffu, s, o);
    if ((t & 31) == 0) s_red[t >> 5] = s;
    __syncthreads();
    float T = 0.f;
    #pragma unroll
    for (int i = 0; i < 8; i++) T += s_red[i];
    float inv = 1.0f / T;

    if (t < 250) {
        float4 o4; o4.x = e0 * inv; o4.y = e1 * inv; o4.z = e2 * inv; o4.w = e3 * inv;
        reinterpret_cast<float4*>(out + (size_t)b * NUM_CLASSES)[t] = o4;
    }
}

// ---------------------------------------------------------------------------
extern "C" void kernel_launch(void* const* d_in, const int* in_sizes, int n_in,
                              void* d_out, int out_size) {
    const float* x    = (const float*)d_in[0];  // (4096, 10000) f32
    const float* W    = (const float*)d_in[1];  // (10000, 1000) f32
    const float* bias = (const float*)d_in[2];  // (1000,) f32
    float* out = (float*)d_out;                 // (4096, 1000) f32

    k3_scan<<<BATCH, 256>>>(x);
    k1_prep<<<dim3(4, NUM_GROUPS), 256>>>(W);
    k2_const<<<4, 256>>>(bias);
    k4_gather<<<dim3(16, 8), 1024>>>();
    k5_softmax<<<BATCH, 256>>>(out);
}